// round 5
// baseline (speedup 1.0000x reference)
#include <cuda_runtime.h>
#include <cuda_bf16.h>

// Problem constants
#define BB   4
#define SS   2048
#define DM   1024
#define HH   16
#define DH   64
#define ROWS (BB*SS)          // 8192
#define OUTE  8388608LL       // B*S*DM
#define ATTNE 268435456LL     // B*H*S*S

typedef unsigned long long ull;

// ---------------- f32x2 helpers (full-rate FP32 on sm_103a) ----------------
__device__ __forceinline__ ull pk(float x, float y) {
    ull r; asm("mov.b64 %0, {%1, %2};" : "=l"(r) : "f"(x), "f"(y)); return r;
}
__device__ __forceinline__ ull fma2_(ull a, ull b, ull c) {
    ull d; asm("fma.rn.f32x2 %0, %1, %2, %3;" : "=l"(d) : "l"(a), "l"(b), "l"(c)); return d;
}
__device__ __forceinline__ float2 upk(ull v) {
    float2 r; asm("mov.b64 {%0, %1}, %2;" : "=f"(r.x), "=f"(r.y) : "l"(v)); return r;
}

// ---------------- scratch (device globals: no allocation allowed) ----------
__device__ float g_Q[ROWS*DM];
__device__ float g_K[ROWS*DM];
__device__ float g_V[ROWS*DM];
__device__ float g_ctx[ROWS*DM];

// ---------------- SGEMM: C = (A @ W + bias) * scale ------------------------
// A: [8192,1024] row-major, W: [1024,1024] row-major.
// head_mode=1: write [B,H,S,DH] layout; head_mode=0: plain row-major.
// BM=128, BN=64, BK=16, 256 threads, thread tile 8x4 (4 row-pairs x 4 cols).
__global__ void __launch_bounds__(256) gemm128x64(
    const float* __restrict__ A, const float* __restrict__ W,
    const float* __restrict__ bias, float* __restrict__ out,
    float scale, int head_mode)
{
    __shared__ float As[16][132];       // transposed A tile, padded
    __shared__ ull   Bs2[16][64];       // W tile, each value duplicated in a pair

    const int Kd = DM, Nd = DM;
    int tid   = threadIdx.x;
    int rbase = blockIdx.y * 128;
    int nbase = blockIdx.x * 64;
    int tm = tid >> 4;   // 0..15 -> row group of 8
    int tn = tid & 15;   // 0..15 -> col group of 4

    ull acc[4][4];
    #pragma unroll
    for (int i = 0; i < 4; i++)
        #pragma unroll
        for (int j = 0; j < 4; j++) acc[i][j] = 0ULL;

    for (int kt = 0; kt < Kd; kt += 16) {
        // A tile: 128 rows x 16 cols = 512 float4
        #pragma unroll
        for (int q = 0; q < 2; q++) {
            int id = tid * 2 + q;
            int r  = id >> 2, c4 = id & 3;
            float4 v = *(const float4*)&A[(size_t)(rbase + r) * Kd + kt + c4 * 4];
            As[c4*4+0][r] = v.x; As[c4*4+1][r] = v.y;
            As[c4*4+2][r] = v.z; As[c4*4+3][r] = v.w;
        }
        // W tile: 16 x 64, duplicated pairs
        {
            int kr = tid >> 4, c4 = tid & 15;
            float4 v = *(const float4*)&W[(size_t)(kt + kr) * Nd + nbase + c4 * 4];
            Bs2[kr][c4*4+0] = pk(v.x, v.x);
            Bs2[kr][c4*4+1] = pk(v.y, v.y);
            Bs2[kr][c4*4+2] = pk(v.z, v.z);
            Bs2[kr][c4*4+3] = pk(v.w, v.w);
        }
        __syncthreads();
        #pragma unroll
        for (int k = 0; k < 16; k++) {
            ulonglong2 a0 = *(const ulonglong2*)&As[k][tm * 8];
            ulonglong2 a1 = *(const ulonglong2*)&As[k][tm * 8 + 4];
            ulonglong2 b0 = *(const ulonglong2*)&Bs2[k][tn * 4];
            ulonglong2 b1 = *(const ulonglong2*)&Bs2[k][tn * 4 + 2];
            ull am[4] = {a0.x, a0.y, a1.x, a1.y};
            ull bn[4] = {b0.x, b0.y, b1.x, b1.y};
            #pragma unroll
            for (int mp = 0; mp < 4; mp++)
                #pragma unroll
                for (int n = 0; n < 4; n++)
                    acc[mp][n] = fma2_(am[mp], bn[n], acc[mp][n]);
        }
        __syncthreads();
    }

    float bb[4];
    #pragma unroll
    for (int n = 0; n < 4; n++) bb[n] = bias[nbase + tn * 4 + n];

    #pragma unroll
    for (int mp = 0; mp < 4; mp++) {
        int r0 = rbase + tm * 8 + mp * 2;
        #pragma unroll
        for (int n = 0; n < 4; n++) {
            float2 p = upk(acc[mp][n]);
            int col = nbase + tn * 4 + n;
            float v0 = (p.x + bb[n]) * scale;
            float v1 = (p.y + bb[n]) * scale;
            if (head_mode) {
                int bi = r0 >> 11;          // / 2048
                int s0 = r0 & 2047;
                int hh = col >> 6, dd = col & 63;
                size_t base = ((size_t)(bi * HH + hh) * SS + s0) * DH + dd;
                out[base]      = v0;
                out[base + DH] = v1;        // s0+1 (tiles never cross batch)
            } else {
                out[(size_t)r0 * Nd + col]       = v0;
                out[(size_t)(r0 + 1) * Nd + col] = v1;
            }
        }
    }
}

// ---------------- attention: scores + softmax + attn write + attn@V --------
// grid (S/16, H, B), 256 threads. smem: sc[16][2048] + qs[16][64] + 2x kv[128][68]
#define QT 16
#define JT 128
#define NJT (SS/JT)
#define KVPAD 68
#define ATTN_SMEM ((QT*SS + QT*DH + 2*JT*KVPAD) * 4)   // 204800 bytes

__global__ void __launch_bounds__(256) attn_kernel(
    const float* __restrict__ Qp, const float* __restrict__ Kp,
    const float* __restrict__ Vp, float* __restrict__ attn_out,
    float* __restrict__ ctx, int write_attn)
{
    extern __shared__ float smem[];
    float* sc  = smem;                    // 16*2048
    float* qs  = smem + QT * SS;          // 16*64
    float* kv0 = qs + QT * DH;            // 128*68
    float* kv1 = kv0 + JT * KVPAD;

    int tid = threadIdx.x;
    int b = blockIdx.z, h = blockIdx.y, qt = blockIdx.x;
    size_t bh = (size_t)b * HH + h;
    const float* Qb = Qp + (bh * SS + (size_t)qt * QT) * DH;
    const float* Kb = Kp + bh * SS * DH;
    const float* Vb = Vp + bh * SS * DH;

    // Q tile: 1024 floats flat
    *(float4*)&qs[tid * 4] = *(const float4*)&Qb[tid * 4];
    // K tile 0 -> kv0 (32KB, coalesced, padded rows)
    {
        const float4* g = (const float4*)Kb;
        #pragma unroll
        for (int r = 0; r < 8; r++) {
            int idx = tid + r * 256;
            int row = idx >> 4, c4 = idx & 15;
            *(float4*)&kv0[row * KVPAD + c4 * 4] = g[idx];
        }
    }
    __syncthreads();

    int wi = tid >> 5;   // warp 0..7
    int tj = tid & 31;

    // ---- scores: 16 x 2048 in j-tiles of 128, K double-buffered ----
    for (int jt = 0; jt < NJT; jt++) {
        float* cur = (jt & 1) ? kv1 : kv0;
        float* nxt = (jt & 1) ? kv0 : kv1;
        bool pre = (jt + 1 < NJT);
        float4 stage[8];
        if (pre) {
            const float4* g = (const float4*)(Kb + (size_t)(jt + 1) * JT * DH);
            #pragma unroll
            for (int r = 0; r < 8; r++) stage[r] = g[tid + r * 256];
        }
        ull acc2[2][4];
        #pragma unroll
        for (int ii = 0; ii < 2; ii++)
            #pragma unroll
            for (int jj = 0; jj < 4; jj++) acc2[ii][jj] = 0ULL;

        #pragma unroll
        for (int d4 = 0; d4 < 16; d4++) {
            ulonglong2 q0 = *(const ulonglong2*)&qs[wi * DH + d4 * 4];
            ulonglong2 q1 = *(const ulonglong2*)&qs[(wi + 8) * DH + d4 * 4];
            #pragma unroll
            for (int jj = 0; jj < 4; jj++) {
                ulonglong2 kk = *(const ulonglong2*)&cur[(tj + jj * 32) * KVPAD + d4 * 4];
                acc2[0][jj] = fma2_(q0.x, kk.x, acc2[0][jj]);
                acc2[0][jj] = fma2_(q0.y, kk.y, acc2[0][jj]);
                acc2[1][jj] = fma2_(q1.x, kk.x, acc2[1][jj]);
                acc2[1][jj] = fma2_(q1.y, kk.y, acc2[1][jj]);
            }
        }
        #pragma unroll
        for (int ii = 0; ii < 2; ii++)
            #pragma unroll
            for (int jj = 0; jj < 4; jj++) {
                float2 p = upk(acc2[ii][jj]);
                sc[(size_t)(wi + ii * 8) * SS + jt * JT + tj + jj * 32] = p.x + p.y;
            }
        if (pre) {
            #pragma unroll
            for (int r = 0; r < 8; r++) {
                int idx = tid + r * 256;
                int row = idx >> 4, c4 = idx & 15;
                *(float4*)&nxt[row * KVPAD + c4 * 4] = stage[r];
            }
        }
        __syncthreads();
    }

    // ---- V tile 0 preload (kv0 is free: last K tile lives in kv1) ----
    {
        const float4* g = (const float4*)Vb;
        #pragma unroll
        for (int r = 0; r < 8; r++) {
            int idx = tid + r * 256;
            int row = idx >> 4, c4 = idx & 15;
            *(float4*)&kv0[row * KVPAD + c4 * 4] = g[idx];
        }
    }

    // ---- softmax: warp wi handles rows wi and wi+8 (warp-local) ----
    #pragma unroll
    for (int ii = 0; ii < 2; ii++) {
        float4* row4 = (float4*)(sc + (size_t)(wi + ii * 8) * SS);
        float m = -3.4e38f;
        for (int j = tj; j < SS / 4; j += 32) {
            float4 t = row4[j];
            m = fmaxf(m, fmaxf(fmaxf(t.x, t.y), fmaxf(t.z, t.w)));
        }
        #pragma unroll
        for (int o = 16; o; o >>= 1) m = fmaxf(m, __shfl_xor_sync(0xffffffffu, m, o));
        float sum = 0.f;
        for (int j = tj; j < SS / 4; j += 32) {
            float4 t = row4[j];
            t.x = __expf(t.x - m); t.y = __expf(t.y - m);
            t.z = __expf(t.z - m); t.w = __expf(t.w - m);
            row4[j] = t;
            sum += t.x + t.y + t.z + t.w;
        }
        #pragma unroll
        for (int o = 16; o; o >>= 1) sum += __shfl_xor_sync(0xffffffffu, sum, o);
        float inv = 1.f / sum;
        for (int j = tj; j < SS / 4; j += 32) {
            float4 t = row4[j];
            t.x *= inv; t.y *= inv; t.z *= inv; t.w *= inv;
            row4[j] = t;
        }
    }
    __syncthreads();

    // ---- write attention probabilities (16 rows contiguous) ----
    if (write_attn) {
        float4* dst = (float4*)(attn_out + (bh * SS + (size_t)qt * QT) * SS);
        const float4* src = (const float4*)sc;
        #pragma unroll
        for (int r = 0; r < 32; r++) dst[tid + r * 256] = src[tid + r * 256];
    }

    // ---- attn @ V : thread owns (row i, 4 consecutive d) ----
    int i  = tid >> 4;      // 0..15
    int dq = tid & 15;      // d quad
    ull o0 = 0ULL, o1 = 0ULL;
    for (int jt = 0; jt < NJT; jt++) {
        float* cur = (jt & 1) ? kv1 : kv0;
        float* nxt = (jt & 1) ? kv0 : kv1;
        bool pre = (jt + 1 < NJT);
        float4 stage[8];
        if (pre) {
            const float4* g = (const float4*)(Vb + (size_t)(jt + 1) * JT * DH);
            #pragma unroll
            for (int r = 0; r < 8; r++) stage[r] = g[tid + r * 256];
        }
        const float* prow = sc + (size_t)i * SS + jt * JT;
        #pragma unroll 4
        for (int j = 0; j < JT; j++) {
            float p = prow[j];
            ull pp = pk(p, p);
            ulonglong2 v = *(const ulonglong2*)&cur[j * KVPAD + dq * 4];
            o0 = fma2_(pp, v.x, o0);
            o1 = fma2_(pp, v.y, o1);
        }
        if (pre) {
            #pragma unroll
            for (int r = 0; r < 8; r++) {
                int idx = tid + r * 256;
                int row = idx >> 4, c4 = idx & 15;
                *(float4*)&nxt[row * KVPAD + c4 * 4] = stage[r];
            }
        }
        __syncthreads();
    }
    float2 lo = upk(o0), hi = upk(o1);
    float4 res = make_float4(lo.x, lo.y, hi.x, hi.y);
    *(float4*)&ctx[((size_t)b * SS + (size_t)qt * QT + i) * DM + h * DH + dq * 4] = res;
}

// ---------------------------------------------------------------------------
extern "C" void kernel_launch(void* const* d_in, const int* in_sizes, int n_in,
                              void* d_out, int out_size)
{
    const float* q  = (const float*)d_in[0];
    const float* k  = (const float*)d_in[1];
    const float* v  = (const float*)d_in[2];
    const float* Wq = (const float*)d_in[3];
    const float* bq = (const float*)d_in[4];
    const float* Wk = (const float*)d_in[5];
    const float* bk = (const float*)d_in[6];
    const float* Wv = (const float*)d_in[7];
    const float* bv = (const float*)d_in[8];
    const float* Wo = (const float*)d_in[9];
    const float* bo = (const float*)d_in[10];

    float* outp = (float*)d_out;
    float* final_dst = nullptr;
    float* attn_dst  = nullptr;
    int write_attn = 0;
    long long osz = (long long)out_size;
    if (osz >= OUTE + ATTNE) {            // (out, attn) concatenated
        final_dst = outp;
        attn_dst  = outp + OUTE;
        write_attn = 1;
    } else if (osz == ATTNE) {            // attn only
        attn_dst = outp;
        write_attn = 1;
    } else {                              // out only
        final_dst = outp;
    }

    float *pQ, *pK, *pV, *pC;
    cudaGetSymbolAddress((void**)&pQ, g_Q);
    cudaGetSymbolAddress((void**)&pK, g_K);
    cudaGetSymbolAddress((void**)&pV, g_V);
    cudaGetSymbolAddress((void**)&pC, g_ctx);

    cudaFuncSetAttribute(attn_kernel, cudaFuncAttributeMaxDynamicSharedMemorySize,
                         ATTN_SMEM);

    dim3 gb(DM / 64, ROWS / 128);
    const float qscale = 0.125f;  // 1/sqrt(DH)
    gemm128x64<<<gb, 256>>>(q, Wq, bq, pQ, qscale, 1);
    gemm128x64<<<gb, 256>>>(k, Wk, bk, pK, 1.0f,   1);
    gemm128x64<<<gb, 256>>>(v, Wv, bv, pV, 1.0f,   1);

    dim3 ga(SS / QT, HH, BB);
    attn_kernel<<<ga, 256, ATTN_SMEM>>>(pQ, pK, pV, attn_dst, pC, write_attn);

    if (final_dst)
        gemm128x64<<<gb, 256>>>(pC, Wo, bo, final_dst, 1.0f, 0);
}

// round 11
// speedup vs baseline: 3.2638x; 3.2638x over previous
#include <cuda_runtime.h>
#include <cuda_bf16.h>
#include <cstdint>

#define BB   4
#define SS   2048
#define DM   1024
#define HH   16
#define DH   64
#define ROWS (BB*SS)          // 8192
#define OUTE  8388608LL
#define ATTNE 268435456LL

// ====================== PTX helpers (sm_80-compatible) ======================
__device__ __forceinline__ uint32_t smem_u32(const void* p) {
    uint32_t a;
    asm("{ .reg .u64 t; cvta.to.shared.u64 t, %1; cvt.u32.u64 %0, t; }"
        : "=r"(a) : "l"(p));
    return a;
}
__device__ __forceinline__ void ldm_x4(uint32_t& r0, uint32_t& r1, uint32_t& r2,
                                       uint32_t& r3, uint32_t a) {
    asm volatile("ldmatrix.sync.aligned.m8n8.x4.shared.b16 {%0,%1,%2,%3}, [%4];"
        : "=r"(r0), "=r"(r1), "=r"(r2), "=r"(r3) : "r"(a));
}
__device__ __forceinline__ void ldm_x2(uint32_t& r0, uint32_t& r1, uint32_t a) {
    asm volatile("ldmatrix.sync.aligned.m8n8.x2.shared.b16 {%0,%1}, [%2];"
        : "=r"(r0), "=r"(r1) : "r"(a));
}
__device__ __forceinline__ void ldm_x2t(uint32_t& r0, uint32_t& r1, uint32_t a) {
    asm volatile("ldmatrix.sync.aligned.m8n8.x2.trans.shared.b16 {%0,%1}, [%2];"
        : "=r"(r0), "=r"(r1) : "r"(a));
}
__device__ __forceinline__ void mma16816(float* c, const uint32_t* a, const uint32_t* b) {
    asm volatile("mma.sync.aligned.m16n8k16.row.col.f32.bf16.bf16.f32 "
        "{%0,%1,%2,%3}, {%4,%5,%6,%7}, {%8,%9}, {%0,%1,%2,%3};"
        : "+f"(c[0]), "+f"(c[1]), "+f"(c[2]), "+f"(c[3])
        : "r"(a[0]), "r"(a[1]), "r"(a[2]), "r"(a[3]), "r"(b[0]), "r"(b[1]));
}
__device__ __forceinline__ void cpa16(uint32_t s, const void* g) {
    asm volatile("cp.async.cg.shared.global [%0], [%1], 16;" :: "r"(s), "l"(g));
}
#define CP_COMMIT() asm volatile("cp.async.commit_group;" ::: "memory")
#define CP_WAIT(n)  asm volatile("cp.async.wait_group %0;" :: "n"(n) : "memory")

__device__ __forceinline__ void split2(float a, float b, uint32_t& hi, uint32_t& lo) {
    __nv_bfloat16 ha = __float2bfloat16(a), hb = __float2bfloat16(b);
    float ra = a - __bfloat162float(ha), rb = b - __bfloat162float(hb);
    __nv_bfloat162 H; H.x = ha; H.y = hb;
    __nv_bfloat162 L; L.x = __float2bfloat16(ra); L.y = __float2bfloat16(rb);
    hi = *reinterpret_cast<uint32_t*>(&H);
    lo = *reinterpret_cast<uint32_t*>(&L);
}

// ====================== device scratch ======================================
__device__ __nv_bfloat16 g_Ihi[3][ROWS*DM], g_Ilo[3][ROWS*DM];
__device__ __nv_bfloat16 g_Whi[4][DM*DM],   g_Wlo[4][DM*DM];   // W^T [n][k]
__device__ __nv_bfloat16 g_Qhi[ROWS*DM], g_Qlo[ROWS*DM];       // [bh][s][64]
__device__ __nv_bfloat16 g_Khi[ROWS*DM], g_Klo[ROWS*DM];
__device__ __nv_bfloat16 g_Vhi[ROWS*DM], g_Vlo[ROWS*DM];       // [bh][s][64]
__device__ __nv_bfloat16 g_Chi[ROWS*DM], g_Clo[ROWS*DM];       // ctx [b][s][1024]
__device__ __nv_bfloat16 g_Phi[268435456], g_Plo[268435456];   // attn probs
__device__ float g_S[268435456];                               // fallback scores

// ====================== split kernels =======================================
__global__ void __launch_bounds__(256) split_rm(
    const float* __restrict__ X, __nv_bfloat16* __restrict__ hi,
    __nv_bfloat16* __restrict__ lo, int n4)
{
    int i = blockIdx.x * 256 + threadIdx.x;
    if (i >= n4) return;
    float4 v = ((const float4*)X)[i];
    uint32_t h0, l0, h1, l1;
    split2(v.x, v.y, h0, l0);
    split2(v.z, v.w, h1, l1);
    ((uint2*)hi)[i] = make_uint2(h0, h1);
    ((uint2*)lo)[i] = make_uint2(l0, l1);
}

// W[K=1024][N=1024] -> T[N][K] hi/lo
__global__ void __launch_bounds__(256) split_w(
    const float* __restrict__ W, __nv_bfloat16* __restrict__ Thi,
    __nv_bfloat16* __restrict__ Tlo)
{
    __shared__ float ts[32][33];
    int c0 = blockIdx.x * 32, r0 = blockIdx.y * 32;
    int tx = threadIdx.x & 31, ty = threadIdx.x >> 5;
    #pragma unroll
    for (int i = 0; i < 4; i++)
        ts[ty + i*8][tx] = W[(size_t)(r0 + ty + i*8) * DM + c0 + tx];
    __syncthreads();
    #pragma unroll
    for (int i = 0; i < 4; i++) {
        int nn = ty + i*8;
        float x = ts[tx][nn];
        __nv_bfloat16 h = __float2bfloat16(x);
        __nv_bfloat16 l = __float2bfloat16(x - __bfloat162float(h));
        size_t o = (size_t)(c0 + nn) * DM + r0 + tx;
        Thi[o] = h; Tlo[o] = l;
    }
}

// ====================== projection GEMM (mma.sync) ==========================
// C[8192x1024] = A(hi/lo)[M][K] @ B(hi/lo)[N][K]^T ; BM=BN=128, BK=32
// 256 thr, 8 warps 2(M)x4(N), warp tile 64x32. mode 0: head bf16 hi/lo, 1: fp32.
__global__ void __launch_bounds__(256) gemm_proj_mma(
    const __nv_bfloat16* __restrict__ Ahi, const __nv_bfloat16* __restrict__ Alo,
    const __nv_bfloat16* __restrict__ Bhi, const __nv_bfloat16* __restrict__ Blo,
    const float* __restrict__ bias, float scale, int mode,
    float* __restrict__ outf, __nv_bfloat16* __restrict__ Ohi,
    __nv_bfloat16* __restrict__ Olo)
{
    extern __shared__ char sm[];
    const int tid = threadIdx.x, warp = tid >> 5, lane = tid & 31;
    const int m0 = blockIdx.y * 128, nb0 = blockIdx.x * 128;
    const int wm = (warp >> 2) * 64, wn = (warp & 3) * 32;
    const uint32_t smb = smem_u32(sm);

    float acc[4][4][4];
    #pragma unroll
    for (int i = 0; i < 4; i++)
        #pragma unroll
        for (int j = 0; j < 4; j++)
            #pragma unroll
            for (int q = 0; q < 4; q++) acc[i][j][q] = 0.f;

    const int lrow = tid >> 1, lk0 = (tid & 1) * 2;
    const size_t gA = (size_t)(m0 + lrow) * DM + lk0 * 8;
    const size_t gB = (size_t)(nb0 + lrow) * DM + lk0 * 8;
    const uint32_t sA0 = (uint32_t)(lrow*4 + ((lk0)   ^ (lrow & 3))) << 4;
    const uint32_t sA1 = (uint32_t)(lrow*4 + ((lk0+1) ^ (lrow & 3))) << 4;

#define PJ_PREFETCH(kc, st) do { \
    uint32_t b_ = smb + (st) * 32768; \
    const __nv_bfloat16* a0_ = Ahi + gA + (kc)*32; \
    const __nv_bfloat16* a1_ = Alo + gA + (kc)*32; \
    const __nv_bfloat16* b0_ = Bhi + gB + (kc)*32; \
    const __nv_bfloat16* b1_ = Blo + gB + (kc)*32; \
    cpa16(b_ + sA0, a0_);          cpa16(b_ + sA1, a0_ + 8); \
    cpa16(b_ + 8192  + sA0, a1_);  cpa16(b_ + 8192  + sA1, a1_ + 8); \
    cpa16(b_ + 16384 + sA0, b0_);  cpa16(b_ + 16384 + sA1, b0_ + 8); \
    cpa16(b_ + 24576 + sA0, b1_);  cpa16(b_ + 24576 + sA1, b1_ + 8); \
} while (0)

    PJ_PREFETCH(0, 0); CP_COMMIT();
    for (int kc = 0; kc < 32; kc++) {
        if (kc + 1 < 32) { PJ_PREFETCH(kc + 1, (kc + 1) & 1); CP_COMMIT(); CP_WAIT(1); }
        else CP_WAIT(0);
        __syncthreads();
        const uint32_t ab = smb + (kc & 1) * 32768;
        #pragma unroll
        for (int ks = 0; ks < 2; ks++) {
            uint32_t Ah[4][4], Al[4][4], Bh[4][2], Bl[4][2];
            #pragma unroll
            for (int mf = 0; mf < 4; mf++) {
                int r = wm + mf*16 + (lane & 15);
                int ku = ks*2 + (lane >> 4);
                uint32_t ad = ab + ((uint32_t)(r*4 + (ku ^ (r & 3))) << 4);
                ldm_x4(Ah[mf][0], Ah[mf][1], Ah[mf][2], Ah[mf][3], ad);
                ldm_x4(Al[mf][0], Al[mf][1], Al[mf][2], Al[mf][3], ad + 8192);
            }
            #pragma unroll
            for (int nf = 0; nf < 4; nf++) {
                int r = wn + nf*8 + (lane & 7);
                int ku = ks*2 + ((lane >> 3) & 1);
                uint32_t bd = ab + 16384 + ((uint32_t)(r*4 + (ku ^ (r & 3))) << 4);
                ldm_x2(Bh[nf][0], Bh[nf][1], bd);
                ldm_x2(Bl[nf][0], Bl[nf][1], bd + 8192);
            }
            #pragma unroll
            for (int mf = 0; mf < 4; mf++)
                #pragma unroll
                for (int nf = 0; nf < 4; nf++) {
                    mma16816(acc[mf][nf], Ah[mf], Bh[nf]);
                    mma16816(acc[mf][nf], Al[mf], Bh[nf]);
                    mma16816(acc[mf][nf], Ah[mf], Bl[nf]);
                }
        }
        __syncthreads();
    }
#undef PJ_PREFETCH

    float bnv[4][2];
    #pragma unroll
    for (int nf = 0; nf < 4; nf++) {
        int n = nb0 + wn + nf*8 + (lane & 3)*2;
        bnv[nf][0] = bias[n]; bnv[nf][1] = bias[n+1];
    }
    #pragma unroll
    for (int mf = 0; mf < 4; mf++)
        #pragma unroll
        for (int nf = 0; nf < 4; nf++) {
            int n = nb0 + wn + nf*8 + (lane & 3)*2;
            #pragma unroll
            for (int hf = 0; hf < 2; hf++) {
                int row = m0 + wm + mf*16 + (lane >> 2) + hf*8;
                float v0 = (acc[mf][nf][hf*2+0] + bnv[nf][0]) * scale;
                float v1 = (acc[mf][nf][hf*2+1] + bnv[nf][1]) * scale;
                if (mode == 0) {
                    int b = row >> 11, s = row & 2047, h = n >> 6, d = n & 63;
                    size_t o = (((size_t)(b*16 + h))*2048 + s)*64 + d;
                    uint32_t H, L; split2(v0, v1, H, L);
                    *(uint32_t*)(Ohi + o) = H;
                    *(uint32_t*)(Olo + o) = L;
                } else {
                    *(float2*)(outf + (size_t)row*DM + n) = make_float2(v0, v1);
                }
            }
        }
}

// ====================== scores GEMM =========================================
// S[bh][m0..+128][n0..+128] = Q @ K^T (raw fp32). Single stage, K=64.
__global__ void __launch_bounds__(256) gemm_scores_mma(
    const __nv_bfloat16* __restrict__ Qhi, const __nv_bfloat16* __restrict__ Qlo,
    const __nv_bfloat16* __restrict__ Khi, const __nv_bfloat16* __restrict__ Klo,
    float* __restrict__ S)
{
    extern __shared__ char sm[];
    const int tid = threadIdx.x, warp = tid >> 5, lane = tid & 31;
    const int n0 = blockIdx.x * 128, m0 = blockIdx.y * 128;
    const size_t bh = blockIdx.z;
    const int wm = (warp >> 2) * 64, wn = (warp & 3) * 32;
    const uint32_t smb = smem_u32(sm);

    const int lrow = tid >> 1, lk0 = (tid & 1) * 4;
    const __nv_bfloat16* Qh = Qhi + (bh*2048 + m0 + lrow)*64 + lk0*8;
    const __nv_bfloat16* Ql = Qlo + (bh*2048 + m0 + lrow)*64 + lk0*8;
    const __nv_bfloat16* Kh = Khi + (bh*2048 + n0 + lrow)*64 + lk0*8;
    const __nv_bfloat16* Kl = Klo + (bh*2048 + n0 + lrow)*64 + lk0*8;
    #pragma unroll
    for (int u = 0; u < 4; u++) {
        uint32_t so = (uint32_t)(lrow*8 + ((lk0 + u) ^ (lrow & 7))) << 4;
        cpa16(smb + so,          Qh + u*8);
        cpa16(smb + 16384 + so,  Ql + u*8);
        cpa16(smb + 32768 + so,  Kh + u*8);
        cpa16(smb + 49152 + so,  Kl + u*8);
    }
    CP_COMMIT(); CP_WAIT(0);
    __syncthreads();

    float acc[4][4][4];
    #pragma unroll
    for (int i = 0; i < 4; i++)
        #pragma unroll
        for (int j = 0; j < 4; j++)
            #pragma unroll
            for (int q = 0; q < 4; q++) acc[i][j][q] = 0.f;

    #pragma unroll
    for (int ks = 0; ks < 4; ks++) {
        uint32_t Ah[4][4], Al[4][4], Bh[4][2], Bl[4][2];
        #pragma unroll
        for (int mf = 0; mf < 4; mf++) {
            int r = wm + mf*16 + (lane & 15);
            int ku = ks*2 + (lane >> 4);
            uint32_t ad = smb + ((uint32_t)(r*8 + (ku ^ (r & 7))) << 4);
            ldm_x4(Ah[mf][0], Ah[mf][1], Ah[mf][2], Ah[mf][3], ad);
            ldm_x4(Al[mf][0], Al[mf][1], Al[mf][2], Al[mf][3], ad + 16384);
        }
        #pragma unroll
        for (int nf = 0; nf < 4; nf++) {
            int r = wn + nf*8 + (lane & 7);
            int ku = ks*2 + ((lane >> 3) & 1);
            uint32_t bd = smb + 32768 + ((uint32_t)(r*8 + (ku ^ (r & 7))) << 4);
            ldm_x2(Bh[nf][0], Bh[nf][1], bd);
            ldm_x2(Bl[nf][0], Bl[nf][1], bd + 16384);
        }
        #pragma unroll
        for (int mf = 0; mf < 4; mf++)
            #pragma unroll
            for (int nf = 0; nf < 4; nf++) {
                mma16816(acc[mf][nf], Ah[mf], Bh[nf]);
                mma16816(acc[mf][nf], Al[mf], Bh[nf]);
                mma16816(acc[mf][nf], Ah[mf], Bl[nf]);
            }
    }

    float* Sb = S + (bh*2048 + (size_t)m0)*2048 + n0;
    #pragma unroll
    for (int mf = 0; mf < 4; mf++)
        #pragma unroll
        for (int nf = 0; nf < 4; nf++) {
            int n = wn + nf*8 + (lane & 3)*2;
            #pragma unroll
            for (int hf = 0; hf < 2; hf++) {
                int m = wm + mf*16 + (lane >> 2) + hf*8;
                *(float2*)(Sb + (size_t)m*2048 + n) =
                    make_float2(acc[mf][nf][hf*2+0], acc[mf][nf][hf*2+1]);
            }
        }
}

// ====================== softmax (in place + bf16 hi/lo P) ===================
__global__ void __launch_bounds__(256) softmax_k(
    float* __restrict__ S, __nv_bfloat16* __restrict__ Phi,
    __nv_bfloat16* __restrict__ Plo, int writeP)
{
    size_t rowi = (size_t)blockIdx.x * 8 + (threadIdx.x >> 5);
    int lane = threadIdx.x & 31;
    float4* row = (float4*)(S + rowi * 2048);
    float4 f[16];
    #pragma unroll
    for (int i = 0; i < 16; i++) f[i] = row[i*32 + lane];
    float m = -3.4e38f;
    #pragma unroll
    for (int i = 0; i < 16; i++)
        m = fmaxf(m, fmaxf(fmaxf(f[i].x, f[i].y), fmaxf(f[i].z, f[i].w)));
    #pragma unroll
    for (int o = 16; o; o >>= 1) m = fmaxf(m, __shfl_xor_sync(0xffffffffu, m, o));
    float sum = 0.f;
    #pragma unroll
    for (int i = 0; i < 16; i++) {
        f[i].x = __expf(f[i].x - m); f[i].y = __expf(f[i].y - m);
        f[i].z = __expf(f[i].z - m); f[i].w = __expf(f[i].w - m);
        sum += f[i].x + f[i].y + f[i].z + f[i].w;
    }
    #pragma unroll
    for (int o = 16; o; o >>= 1) sum += __shfl_xor_sync(0xffffffffu, sum, o);
    float inv = 1.f / sum;
    uint2* ph = (uint2*)(Phi + rowi * 2048);
    uint2* pl = (uint2*)(Plo + rowi * 2048);
    #pragma unroll
    for (int i = 0; i < 16; i++) {
        f[i].x *= inv; f[i].y *= inv; f[i].z *= inv; f[i].w *= inv;
        row[i*32 + lane] = f[i];
        if (writeP) {
            uint32_t h0, l0, h1, l1;
            split2(f[i].x, f[i].y, h0, l0);
            split2(f[i].z, f[i].w, h1, l1);
            ph[i*32 + lane] = make_uint2(h0, h1);
            pl[i*32 + lane] = make_uint2(l0, l1);
        }
    }
}

// ====================== PV GEMM =============================================
// ctx[bh][m0..+128][64] = P @ V ; BM=128, BN=64, BK=64, NC=32, ldmatrix.trans V
__global__ void __launch_bounds__(256) gemm_pv_mma(
    const __nv_bfloat16* __restrict__ Phi, const __nv_bfloat16* __restrict__ Plo,
    const __nv_bfloat16* __restrict__ Vhi, const __nv_bfloat16* __restrict__ Vlo,
    __nv_bfloat16* __restrict__ Chi, __nv_bfloat16* __restrict__ Clo)
{
    extern __shared__ char sm[];
    const int tid = threadIdx.x, warp = tid >> 5, lane = tid & 31;
    const int m0 = blockIdx.x * 128;
    const size_t bh = blockIdx.y;
    const int b = (int)(bh >> 4), h = (int)(bh & 15);
    const int wm = (warp & 3) * 32, wn = (warp >> 2) * 32;
    const uint32_t smb = smem_u32(sm);

    float acc[2][4][4];
    #pragma unroll
    for (int i = 0; i < 2; i++)
        #pragma unroll
        for (int j = 0; j < 4; j++)
            #pragma unroll
            for (int q = 0; q < 4; q++) acc[i][j][q] = 0.f;

    const int prow = tid >> 1, pk0 = (tid & 1) * 4;
    const int vrow = tid >> 2, vk0 = (tid & 3) * 2;
    const size_t gP = (bh*2048 + m0 + prow)*2048 + pk0*8;

#define PV_PREFETCH(kc, st) do { \
    uint32_t b_ = smb + (st) * 49152; \
    const __nv_bfloat16* p0_ = Phi + gP + (kc)*64; \
    const __nv_bfloat16* p1_ = Plo + gP + (kc)*64; \
    size_t gv_ = (bh*2048 + (size_t)(kc)*64 + vrow)*64 + vk0*8; \
    for (int u = 0; u < 4; u++) { \
        uint32_t so = (uint32_t)(prow*8 + ((pk0 + u) ^ (prow & 7))) << 4; \
        cpa16(b_ + so,         p0_ + u*8); \
        cpa16(b_ + 16384 + so, p1_ + u*8); \
    } \
    for (int u = 0; u < 2; u++) { \
        uint32_t so = (uint32_t)(vrow*8 + ((vk0 + u) ^ (vrow & 7))) << 4; \
        cpa16(b_ + 32768 + so, Vhi + gv_ + u*8); \
        cpa16(b_ + 40960 + so, Vlo + gv_ + u*8); \
    } \
} while (0)

    PV_PREFETCH(0, 0); CP_COMMIT();
    for (int kc = 0; kc < 32; kc++) {
        if (kc + 1 < 32) { PV_PREFETCH(kc + 1, (kc + 1) & 1); CP_COMMIT(); CP_WAIT(1); }
        else CP_WAIT(0);
        __syncthreads();
        const uint32_t ab = smb + (kc & 1) * 49152;
        #pragma unroll
        for (int ks = 0; ks < 4; ks++) {
            uint32_t Ah[2][4], Al[2][4], Bh[4][2], Bl[4][2];
            #pragma unroll
            for (int mf = 0; mf < 2; mf++) {
                int r = wm + mf*16 + (lane & 15);
                int ku = ks*2 + (lane >> 4);
                uint32_t ad = ab + ((uint32_t)(r*8 + (ku ^ (r & 7))) << 4);
                ldm_x4(Ah[mf][0], Ah[mf][1], Ah[mf][2], Ah[mf][3], ad);
                ldm_x4(Al[mf][0], Al[mf][1], Al[mf][2], Al[mf][3], ad + 16384);
            }
            #pragma unroll
            for (int nf = 0; nf < 4; nf++) {
                int r = ks*16 + (lane & 15);
                int nu = (wn >> 3) + nf;
                uint32_t bd = ab + 32768 + ((uint32_t)(r*8 + (nu ^ (r & 7))) << 4);
                ldm_x2t(Bh[nf][0], Bh[nf][1], bd);
                ldm_x2t(Bl[nf][0], Bl[nf][1], bd + 8192);
            }
            #pragma unroll
            for (int mf = 0; mf < 2; mf++)
                #pragma unroll
                for (int nf = 0; nf < 4; nf++) {
                    mma16816(acc[mf][nf], Ah[mf], Bh[nf]);
                    mma16816(acc[mf][nf], Al[mf], Bh[nf]);
                    mma16816(acc[mf][nf], Ah[mf], Bl[nf]);
                }
        }
        __syncthreads();
    }
#undef PV_PREFETCH

    #pragma unroll
    for (int mf = 0; mf < 2; mf++)
        #pragma unroll
        for (int nf = 0; nf < 4; nf++) {
            int n = wn + nf*8 + (lane & 3)*2;     // d
            #pragma unroll
            for (int hf = 0; hf < 2; hf++) {
                int m = wm + mf*16 + (lane >> 2) + hf*8;
                size_t o = ((size_t)b*2048 + m0 + m)*1024 + h*64 + n;
                uint32_t H, L;
                split2(acc[mf][nf][hf*2+0], acc[mf][nf][hf*2+1], H, L);
                *(uint32_t*)(Chi + o) = H;
                *(uint32_t*)(Clo + o) = L;
            }
        }
}

// ====================== host ================================================
extern "C" void kernel_launch(void* const* d_in, const int* in_sizes, int n_in,
                              void* d_out, int out_size)
{
    const float* q  = (const float*)d_in[0];
    const float* k  = (const float*)d_in[1];
    const float* v  = (const float*)d_in[2];
    const float* Wq = (const float*)d_in[3];
    const float* bq = (const float*)d_in[4];
    const float* Wk = (const float*)d_in[5];
    const float* bk = (const float*)d_in[6];
    const float* Wv = (const float*)d_in[7];
    const float* bv = (const float*)d_in[8];
    const float* Wo = (const float*)d_in[9];
    const float* bo = (const float*)d_in[10];

    float* outp = (float*)d_out;
    float* final_dst = nullptr;
    float* attn_dst  = nullptr;
    long long osz = (long long)out_size;
    if (osz >= OUTE + ATTNE)      { final_dst = outp; attn_dst = outp + OUTE; }
    else if (osz == ATTNE)        { attn_dst = outp; }
    else                          { final_dst = outp; }

    __nv_bfloat16 *pIhi, *pIlo, *pWhi, *pWlo, *pQhi, *pQlo, *pKhi, *pKlo;
    __nv_bfloat16 *pVhi, *pVlo, *pChi, *pClo, *pPhi, *pPlo;
    float* pS;
    cudaGetSymbolAddress((void**)&pIhi, g_Ihi);
    cudaGetSymbolAddress((void**)&pIlo, g_Ilo);
    cudaGetSymbolAddress((void**)&pWhi, g_Whi);
    cudaGetSymbolAddress((void**)&pWlo, g_Wlo);
    cudaGetSymbolAddress((void**)&pQhi, g_Qhi);
    cudaGetSymbolAddress((void**)&pQlo, g_Qlo);
    cudaGetSymbolAddress((void**)&pKhi, g_Khi);
    cudaGetSymbolAddress((void**)&pKlo, g_Klo);
    cudaGetSymbolAddress((void**)&pVhi, g_Vhi);
    cudaGetSymbolAddress((void**)&pVlo, g_Vlo);
    cudaGetSymbolAddress((void**)&pChi, g_Chi);
    cudaGetSymbolAddress((void**)&pClo, g_Clo);
    cudaGetSymbolAddress((void**)&pPhi, g_Phi);
    cudaGetSymbolAddress((void**)&pPlo, g_Plo);
    cudaGetSymbolAddress((void**)&pS,   g_S);

    float* Sbuf = attn_dst ? attn_dst : pS;

    cudaFuncSetAttribute(gemm_proj_mma,   cudaFuncAttributeMaxDynamicSharedMemorySize, 65536);
    cudaFuncSetAttribute(gemm_scores_mma, cudaFuncAttributeMaxDynamicSharedMemorySize, 65536);
    cudaFuncSetAttribute(gemm_pv_mma,     cudaFuncAttributeMaxDynamicSharedMemorySize, 98304);

    const int n4 = ROWS*DM/4;
    split_rm<<<n4/256, 256>>>(q, pIhi + 0*(size_t)ROWS*DM, pIlo + 0*(size_t)ROWS*DM, n4);
    split_rm<<<n4/256, 256>>>(k, pIhi + 1*(size_t)ROWS*DM, pIlo + 1*(size_t)ROWS*DM, n4);
    split_rm<<<n4/256, 256>>>(v, pIhi + 2*(size_t)ROWS*DM, pIlo + 2*(size_t)ROWS*DM, n4);
    dim3 gw(32, 32);
    split_w<<<gw, 256>>>(Wq, pWhi + 0*(size_t)DM*DM, pWlo + 0*(size_t)DM*DM);
    split_w<<<gw, 256>>>(Wk, pWhi + 1*(size_t)DM*DM, pWlo + 1*(size_t)DM*DM);
    split_w<<<gw, 256>>>(Wv, pWhi + 2*(size_t)DM*DM, pWlo + 2*(size_t)DM*DM);
    split_w<<<gw, 256>>>(Wo, pWhi + 3*(size_t)DM*DM, pWlo + 3*(size_t)DM*DM);

    dim3 gp(8, 64);
    gemm_proj_mma<<<gp, 256, 65536>>>(pIhi, pIlo, pWhi, pWlo,
                                      bq, 0.125f, 0, nullptr, pQhi, pQlo);
    gemm_proj_mma<<<gp, 256, 65536>>>(pIhi + (size_t)ROWS*DM, pIlo + (size_t)ROWS*DM,
                                      pWhi + (size_t)DM*DM, pWlo + (size_t)DM*DM,
                                      bk, 1.0f, 0, nullptr, pKhi, pKlo);
    gemm_proj_mma<<<gp, 256, 65536>>>(pIhi + 2*(size_t)ROWS*DM, pIlo + 2*(size_t)ROWS*DM,
                                      pWhi + 2*(size_t)DM*DM, pWlo + 2*(size_t)DM*DM,
                                      bv, 1.0f, 0, nullptr, pVhi, pVlo);

    dim3 gs(16, 16, 64);
    gemm_scores_mma<<<gs, 256, 65536>>>(pQhi, pQlo, pKhi, pKlo, Sbuf);
    softmax_k<<<16384, 256>>>(Sbuf, pPhi, pPlo, final_dst ? 1 : 0);

    if (final_dst) {
        dim3 gv(16, 64);
        gemm_pv_mma<<<gv, 256, 98304>>>(pPhi, pPlo, pVhi, pVlo, pChi, pClo);
        gemm_proj_mma<<<gp, 256, 65536>>>(pChi, pClo,
                                          pWhi + 3*(size_t)DM*DM, pWlo + 3*(size_t)DM*DM,
                                          bo, 1.0f, 1, final_dst, nullptr, nullptr);
    }
}